// round 9
// baseline (speedup 1.0000x reference)
#include <cuda_runtime.h>
#include <cuda_bf16.h>
#include <cuda_fp16.h>
#include <mma.h>
#include <cstdint>

using namespace nvcuda;

// Problem constants (fixed-shape problem)
#define NN 100000
#define NE 1600000
#define BKT 64                          // bucket capacity per node
#define EPS 1e-16f

// ---------------- scratch (device globals; no allocation allowed) ------------
__device__ __half2 g_h2[NN * 32];   // transformed features, fp16 (64 feats = 32 half2)
__device__ float g_agg[NN * 64];    // aggregated output of layer 1 (fp32)
__device__ float g_ssrc[NN];
__device__ float g_sdst[NN];
__device__ int   g_cnt[NN];         // per-node incoming-edge count
__device__ int   g_bkt[NN * BKT];   // per-node source buckets

__device__ __forceinline__ float leaky(float v) {
    return fmaxf(v, 0.2f * v);   // NEG_SLOPE = 0.2
}

__device__ __forceinline__ float tanh_fast(float v) {
    asm("tanh.approx.f32 %0, %0;" : "+f"(v));
    return v;
}

// ---------------- bucket scatter (replaces hist+scan+scatter) ----------------
__global__ void k_scatter(const int4* __restrict__ src4, const int4* __restrict__ dst4) {
    const int Q = NE / 8;
    int t = blockIdx.x * blockDim.x + threadIdx.x;
    if (t < Q) {
        int4 s0 = src4[t];
        int4 d0 = dst4[t];
        int4 s1 = src4[t + Q];
        int4 d1 = dst4[t + Q];
        int p;
        p = atomicAdd(&g_cnt[d0.x], 1); if (p < BKT) g_bkt[d0.x * BKT + p] = s0.x;
        p = atomicAdd(&g_cnt[d0.y], 1); if (p < BKT) g_bkt[d0.y * BKT + p] = s0.y;
        p = atomicAdd(&g_cnt[d0.z], 1); if (p < BKT) g_bkt[d0.z * BKT + p] = s0.z;
        p = atomicAdd(&g_cnt[d0.w], 1); if (p < BKT) g_bkt[d0.w * BKT + p] = s0.w;
        p = atomicAdd(&g_cnt[d1.x], 1); if (p < BKT) g_bkt[d1.x * BKT + p] = s1.x;
        p = atomicAdd(&g_cnt[d1.y], 1); if (p < BKT) g_bkt[d1.y * BKT + p] = s1.y;
        p = atomicAdd(&g_cnt[d1.z], 1); if (p < BKT) g_bkt[d1.z * BKT + p] = s1.z;
        p = atomicAdd(&g_cnt[d1.w], 1); if (p < BKT) g_bkt[d1.w * BKT + p] = s1.w;
    }
}

// ---------------- h = act(x) @ W via wmma + fused attention scores ----------
__global__ void __launch_bounds__(256) k_lin(
    const float* __restrict__ xin, const float* __restrict__ W,
    const float* __restrict__ b_in, int do_tanh, __half2* __restrict__ hout,
    const float* __restrict__ asrc, const float* __restrict__ adst)
{
    __shared__ __half Xh[64 * 72];
    __shared__ __half Wh[64 * 64];
    __shared__ float  Cs[64 * 72];
    int t = threadIdx.x;
    int row0 = blockIdx.x * 64;

    for (int i = t; i < 4096; i += 256) Wh[i] = __float2half(W[i]);
    for (int i = t; i < 4096; i += 256) {
        int r = i >> 6, c = i & 63;
        float v = 0.f;
        int gr = row0 + r;
        if (gr < NN) {
            v = xin[gr * 64 + c];
            if (do_tanh) v = tanh_fast(v + b_in[c]);
        }
        Xh[r * 72 + c] = __float2half(v);
    }
    __syncthreads();

    int w  = t >> 5;
    int wm = w & 3;     // row group (16 rows)
    int wn = w >> 2;    // col group (32 cols)
    wmma::fragment<wmma::accumulator, 16, 16, 16, float> c0, c1;
    wmma::fill_fragment(c0, 0.f);
    wmma::fill_fragment(c1, 0.f);
#pragma unroll
    for (int k0 = 0; k0 < 64; k0 += 16) {
        wmma::fragment<wmma::matrix_a, 16, 16, 16, __half, wmma::row_major> a;
        wmma::fragment<wmma::matrix_b, 16, 16, 16, __half, wmma::row_major> b0, b1;
        wmma::load_matrix_sync(a, Xh + wm * 16 * 72 + k0, 72);
        wmma::load_matrix_sync(b0, Wh + k0 * 64 + wn * 32, 64);
        wmma::load_matrix_sync(b1, Wh + k0 * 64 + wn * 32 + 16, 64);
        wmma::mma_sync(c0, a, b0, c0);
        wmma::mma_sync(c1, a, b1, c1);
    }
    wmma::store_matrix_sync(Cs + wm * 16 * 72 + wn * 32,      c0, 72, wmma::mem_row_major);
    wmma::store_matrix_sync(Cs + wm * 16 * 72 + wn * 32 + 16, c1, 72, wmma::mem_row_major);
    __syncthreads();

    for (int i = t; i < 2048; i += 256) {
        int r = i >> 5, c2 = i & 31;
        int gr = row0 + r;
        if (gr < NN)
            hout[gr * 32 + c2] =
                __floats2half2_rn(Cs[r * 72 + c2 * 2], Cs[r * 72 + c2 * 2 + 1]);
    }

    int r = t >> 2, q = t & 3;
    const float* crow = &Cs[r * 72 + q * 16];
    float ps = 0.f, pd = 0.f;
#pragma unroll
    for (int j = 0; j < 16; j++) {
        float hv = crow[j];
        ps += hv * asrc[q * 16 + j];
        pd += hv * adst[q * 16 + j];
    }
    ps += __shfl_down_sync(~0u, ps, 2, 4);
    ps += __shfl_down_sync(~0u, ps, 1, 4);
    pd += __shfl_down_sync(~0u, pd, 2, 4);
    pd += __shfl_down_sync(~0u, pd, 1, 4);
    if (q == 0 && row0 + r < NN) {
        g_ssrc[row0 + r] = ps;
        g_sdst[row0 + r] = pd;
    }
}

// ---------------- GAT aggregation: warp per destination node (R6 form) -------
__global__ void __launch_bounds__(256) k_node(const __half2* __restrict__ h2,
                                              float* __restrict__ aggout,
                                              const float* __restrict__ b2,
                                              const float* __restrict__ Wl,
                                              const float* __restrict__ bl,
                                              float* __restrict__ out,
                                              int final_mode)
{
    __shared__ int   sS[8][32];
    __shared__ float sW[8][32];
    int warp = (blockIdx.x * blockDim.x + threadIdx.x) >> 5;
    int lane = threadIdx.x & 31;
    int w8   = (threadIdx.x >> 5) & 7;
    if (warp >= NN) return;
    int i = warp;
    int n  = min(__ldg(&g_cnt[i]), BKT);
    const int* brow = &g_bkt[i * BKT];
    float sd = g_sdst[i];

    float ex = __expf(fminf(leaky(g_ssrc[i] + sd), 60.f));   // self loop
    float2 hs = __half22float2(h2[i * 32 + lane]);
    float ax = ex * hs.x, ay = ex * hs.y;
    float dl = 0.f;

    for (int eb = 0; eb < n; eb += 32) {
        int idx = eb + lane;
        int   s_l = 0;
        float w_l = 0.f;
        if (idx < n) {
            s_l = __ldg(&brow[idx]);
            w_l = __expf(fminf(leaky(g_ssrc[s_l] + sd), 60.f));
        }
        sS[w8][lane] = s_l;
        sW[w8][lane] = w_l;
        dl += w_l;
        __syncwarp();
        int nn = min(32, n - eb);
        int j = 0;
        for (; j + 4 <= nn; j += 4) {
            int   s0 = sS[w8][j],     s1 = sS[w8][j + 1];
            int   s2 = sS[w8][j + 2], s3 = sS[w8][j + 3];
            float w0 = sW[w8][j],     w1 = sW[w8][j + 1];
            float w2 = sW[w8][j + 2], w3 = sW[w8][j + 3];
            float2 f0 = __half22float2(h2[s0 * 32 + lane]);
            float2 f1 = __half22float2(h2[s1 * 32 + lane]);
            float2 f2 = __half22float2(h2[s2 * 32 + lane]);
            float2 f3 = __half22float2(h2[s3 * 32 + lane]);
            ax += w0 * f0.x + w1 * f1.x + w2 * f2.x + w3 * f3.x;
            ay += w0 * f0.y + w1 * f1.y + w2 * f2.y + w3 * f3.y;
        }
        for (; j < nn; j++) {
            int   s0 = sS[w8][j];
            float w0 = sW[w8][j];
            float2 f0 = __half22float2(h2[s0 * 32 + lane]);
            ax += w0 * f0.x;
            ay += w0 * f0.y;
        }
        __syncwarp();
    }
#pragma unroll
    for (int o = 16; o; o >>= 1) dl += __shfl_xor_sync(~0u, dl, o);
    float inv = 1.f / (ex + dl + EPS);

    if (!final_mode) {
        aggout[i * 64 + lane * 2]     = ax * inv;
        aggout[i * 64 + lane * 2 + 1] = ay * inv;
    } else {
        float2 bv = *(const float2*)&b2[lane * 2];
        float2 wv = *(const float2*)&Wl[lane * 2];
        float s = (ax * inv + bv.x) * wv.x + (ay * inv + bv.y) * wv.y;
#pragma unroll
        for (int o = 16; o; o >>= 1) s += __shfl_xor_sync(~0u, s, o);
        if (!lane) out[i] = s + bl[0];
    }
}

// ---------------- launcher ---------------------------------------------------
static cudaStream_t s_csr = nullptr;
static cudaEvent_t  s_evFork = nullptr, s_evJoin = nullptr;

extern "C" void kernel_launch(void* const* d_in, const int* in_sizes, int n_in,
                              void* d_out, int out_size)
{
    const float* x     = (const float*)d_in[0];
    const int*   eidx  = (const int*)d_in[1];
    const float* W1    = (const float*)d_in[2];
    const float* as1   = (const float*)d_in[3];
    const float* ad1   = (const float*)d_in[4];
    const float* b1    = (const float*)d_in[5];
    const float* W2    = (const float*)d_in[6];
    const float* as2   = (const float*)d_in[7];
    const float* ad2   = (const float*)d_in[8];
    const float* b2    = (const float*)d_in[9];
    const float* Wl    = (const float*)d_in[10];
    const float* bl    = (const float*)d_in[11];
    float* out = (float*)d_out;

    const int4* src4 = (const int4*)eidx;
    const int4* dst4 = (const int4*)(eidx + NE);

    __half2* h_ptr = nullptr;
    float* agg_ptr = nullptr;
    void*  cnt_ptr = nullptr;
    cudaGetSymbolAddress((void**)&h_ptr, g_h2);
    cudaGetSymbolAddress((void**)&agg_ptr, g_agg);
    cudaGetSymbolAddress(&cnt_ptr, g_cnt);

    if (!s_csr) {
        cudaStreamCreateWithFlags(&s_csr, cudaStreamNonBlocking);
        cudaEventCreateWithFlags(&s_evFork, cudaEventDisableTiming);
        cudaEventCreateWithFlags(&s_evJoin, cudaEventDisableTiming);
    }

    const int LIN_BLOCKS  = (NN + 63) / 64;          // 1563
    const int WARP_BLOCKS = (NN * 32 + 255) / 256;   // 12500
    const int E8_BLOCKS   = (NE / 8 + 255) / 256;    // 782

    // fork: bucket scatter runs concurrently with layer-1 linear
    cudaEventRecord(s_evFork, 0);
    cudaStreamWaitEvent(s_csr, s_evFork, 0);

    k_lin<<<LIN_BLOCKS, 256>>>(x, W1, nullptr, 0, h_ptr, as1, ad1);

    cudaMemsetAsync(cnt_ptr, 0, NN * sizeof(int), s_csr);
    k_scatter<<<E8_BLOCKS, 256, 0, s_csr>>>(src4, dst4);
    cudaEventRecord(s_evJoin, s_csr);
    cudaStreamWaitEvent(0, s_evJoin, 0);

    // layer-1 aggregation
    k_node<<<WARP_BLOCKS, 256>>>(h_ptr, agg_ptr, nullptr, nullptr, nullptr, nullptr, 0);
    // layer-2 linear (input = tanh(agg1 + b1))
    k_lin<<<LIN_BLOCKS, 256>>>(agg_ptr, W2, b1, 1, h_ptr, as2, ad2);
    // layer-2 aggregation + fused readout
    k_node<<<WARP_BLOCKS, 256>>>(h_ptr, nullptr, b2, Wl, bl, out, 1);
}

// round 10
// speedup vs baseline: 1.0373x; 1.0373x over previous
#include <cuda_runtime.h>
#include <cuda_bf16.h>
#include <cuda_fp16.h>
#include <mma.h>
#include <cstdint>

using namespace nvcuda;

// Problem constants (fixed-shape problem)
#define NN 100000
#define NE 1600000
#define SCAN_NB 98                      // ceil(100000/1024)
#define EPS 1e-16f

// ---------------- scratch (device globals; no allocation allowed) ------------
__device__ __half2 g_h2[NN * 32];   // transformed features, fp16 (64 feats = 32 half2)
__device__ float g_agg[NN * 64];    // aggregated output of layer 1 (fp32)
__device__ float g_ssrc[NN];
__device__ float g_sdst[NN];
__device__ int   g_deg[NN];         // zero-init at load; re-zeroed by k_scan each run
__device__ int   g_cur[NN];         // exclusive prefix -> after scatter: inclusive
__device__ int   g_csrc[NE];
__device__ int   g_bsums[128];
__device__ int   g_done;            // k_scan completion counter (self-resetting)
__device__ int   g_epoch;           // k_scan epoch (monotonic across runs)
__device__ __half g_W1h[64 * 96];   // [W1 | W1@a_src1 | W1@a_dst1 | 0...] fp16
__device__ __half g_W2h[64 * 96];

__device__ __forceinline__ float leaky(float v) {
    return fmaxf(v, 0.2f * v);   // NEG_SLOPE = 0.2
}

__device__ __forceinline__ float tanh_fast(float v) {
    asm("tanh.approx.f32 %0, %0;" : "+f"(v));
    return v;
}

// ---------------- weight prep: build 64x96 fp16 tiles ------------------------
__global__ void k_prep(const float* __restrict__ W1, const float* __restrict__ as1,
                       const float* __restrict__ ad1,
                       const float* __restrict__ W2, const float* __restrict__ as2,
                       const float* __restrict__ ad2)
{
    const float* W  = blockIdx.x ? W2 : W1;
    const float* as = blockIdx.x ? as2 : as1;
    const float* ad = blockIdx.x ? ad2 : ad1;
    __half* Wh = blockIdx.x ? g_W2h : g_W1h;
    int t = threadIdx.x;
    // zero all 96 cols first (cols 66..95 stay zero)
    for (int i = t; i < 64 * 96; i += 256) Wh[i] = __float2half(0.f);
    __syncthreads();
    for (int i = t; i < 4096; i += 256) {
        int k = i >> 6, j = i & 63;
        Wh[k * 96 + j] = __float2half(W[i]);
    }
    if (t < 64) {
        float ds = 0.f, dd = 0.f;
        for (int j = 0; j < 64; j++) {
            float w = W[t * 64 + j];
            ds += w * as[j];
            dd += w * ad[j];
        }
        Wh[t * 96 + 64] = __float2half(ds);
        Wh[t * 96 + 65] = __float2half(dd);
    }
}

// ---------------- histogram of dst (8 independent chains / thread) ----------
__global__ void k_hist(const int4* __restrict__ dst4) {
    const int Q = NE / 8;
    int t = blockIdx.x * blockDim.x + threadIdx.x;
    if (t < Q) {
        int4 d0 = dst4[t];
        int4 d1 = dst4[t + Q];
        atomicAdd(&g_deg[d0.x], 1);
        atomicAdd(&g_deg[d0.y], 1);
        atomicAdd(&g_deg[d0.z], 1);
        atomicAdd(&g_deg[d0.w], 1);
        atomicAdd(&g_deg[d1.x], 1);
        atomicAdd(&g_deg[d1.y], 1);
        atomicAdd(&g_deg[d1.z], 1);
        atomicAdd(&g_deg[d1.w], 1);
    }
}

// ---------------- single-kernel exclusive scan of deg -> g_cur ---------------
__global__ void __launch_bounds__(1024) k_scan() {
    __shared__ int swarp[32];
    __shared__ int sboff[128];
    int t = threadIdx.x, b = blockIdx.x;
    int lane = t & 31, wid = t >> 5;
    int idx = b * 1024 + t;

    int e0 = 0;
    if (t == 0) e0 = *(volatile int*)&g_epoch;   // read BEFORE publishing

    int v = (idx < NN) ? g_deg[idx] : 0;
    if (idx < NN) g_deg[idx] = 0;

    int x = v;
#pragma unroll
    for (int off = 1; off < 32; off <<= 1) {
        int y = __shfl_up_sync(~0u, x, off);
        if (lane >= off) x += y;
    }
    if (lane == 31) swarp[wid] = x;
    __syncthreads();
    if (wid == 0) {
        int s = swarp[lane];
#pragma unroll
        for (int off = 1; off < 32; off <<= 1) {
            int y = __shfl_up_sync(~0u, s, off);
            if (lane >= off) s += y;
        }
        swarp[lane] = s;
    }
    __syncthreads();
    int incl = x + (wid ? swarp[wid - 1] : 0);
    int ex = incl - v;
    int total = swarp[31];

    if (t == 0) {
        g_bsums[b] = total;
        __threadfence();
        int r = atomicAdd(&g_done, 1);
        if (r == SCAN_NB - 1) {
            g_done = 0;
            __threadfence();
            atomicAdd(&g_epoch, 1);
        }
        while (*(volatile int*)&g_epoch == e0) { }
    }
    __syncthreads();

    if (t < 128) sboff[t] = (t < SCAN_NB) ? g_bsums[t] : 0;
    __syncthreads();
    for (int off = 1; off < 128; off <<= 1) {
        int y = 0;
        if (t < 128) { y = sboff[t]; if (t >= off) y += sboff[t - off]; }
        __syncthreads();
        if (t < 128) sboff[t] = y;
        __syncthreads();
    }
    int boff = b ? sboff[b - 1] : 0;
    if (idx < NN) g_cur[idx] = ex + boff;
}

// ---------------- CSR scatter (8 independent chains / thread) ----------------
__global__ void k_scatter(const int4* __restrict__ src4, const int4* __restrict__ dst4) {
    const int Q = NE / 8;
    int t = blockIdx.x * blockDim.x + threadIdx.x;
    if (t < Q) {
        int4 s0 = src4[t];
        int4 d0 = dst4[t];
        int4 s1 = src4[t + Q];
        int4 d1 = dst4[t + Q];
        g_csrc[atomicAdd(&g_cur[d0.x], 1)] = s0.x;
        g_csrc[atomicAdd(&g_cur[d0.y], 1)] = s0.y;
        g_csrc[atomicAdd(&g_cur[d0.z], 1)] = s0.z;
        g_csrc[atomicAdd(&g_cur[d0.w], 1)] = s0.w;
        g_csrc[atomicAdd(&g_cur[d1.x], 1)] = s1.x;
        g_csrc[atomicAdd(&g_cur[d1.y], 1)] = s1.y;
        g_csrc[atomicAdd(&g_cur[d1.z], 1)] = s1.z;
        g_csrc[atomicAdd(&g_cur[d1.w], 1)] = s1.w;
    }
}

// ---------------- fused linear: C[64x96] = act(x)[64x64] @ Wh[64x96] ---------
// cols 0..63 -> h (fp16); col 64 -> ssrc; col 65 -> sdst.
__global__ void __launch_bounds__(256) k_lin(
    const float* __restrict__ xin, const __half* __restrict__ Wg,
    const float* __restrict__ b_in, int do_tanh, __half2* __restrict__ hout)
{
    __shared__ __half Xh[64 * 72];       //  9216 B
    __shared__ __half Wh[64 * 96];       // 12288 B
    __shared__ float  Cs[64 * 100];      // 25600 B  (stride 100 avoids conflicts)
    int t = threadIdx.x;
    int row0 = blockIdx.x * 64;

    // load precomputed weight tile (int4 vectorized: 768 int4)
    {
        const int4* Wsrc = (const int4*)Wg;
        int4* Wdst = (int4*)Wh;
        for (int i = t; i < 768; i += 256) Wdst[i] = Wsrc[i];
    }
    for (int i = t; i < 4096; i += 256) {
        int r = i >> 6, c = i & 63;
        float v = 0.f;
        int gr = row0 + r;
        if (gr < NN) {
            v = xin[gr * 64 + c];
            if (do_tanh) v = tanh_fast(v + b_in[c]);
        }
        Xh[r * 72 + c] = __float2half(v);
    }
    __syncthreads();

    int w  = t >> 5;
    int wm = w & 3;     // row group (16 rows)
    int wn = w >> 2;    // col group (48 cols)
    wmma::fragment<wmma::accumulator, 16, 16, 16, float> c0, c1, c2;
    wmma::fill_fragment(c0, 0.f);
    wmma::fill_fragment(c1, 0.f);
    wmma::fill_fragment(c2, 0.f);
#pragma unroll
    for (int k0 = 0; k0 < 64; k0 += 16) {
        wmma::fragment<wmma::matrix_a, 16, 16, 16, __half, wmma::row_major> a;
        wmma::fragment<wmma::matrix_b, 16, 16, 16, __half, wmma::row_major> b0, b1, b2;
        wmma::load_matrix_sync(a, Xh + wm * 16 * 72 + k0, 72);
        wmma::load_matrix_sync(b0, Wh + k0 * 96 + wn * 48, 96);
        wmma::load_matrix_sync(b1, Wh + k0 * 96 + wn * 48 + 16, 96);
        wmma::load_matrix_sync(b2, Wh + k0 * 96 + wn * 48 + 32, 96);
        wmma::mma_sync(c0, a, b0, c0);
        wmma::mma_sync(c1, a, b1, c1);
        wmma::mma_sync(c2, a, b2, c2);
    }
    wmma::store_matrix_sync(Cs + wm * 16 * 100 + wn * 48,      c0, 100, wmma::mem_row_major);
    wmma::store_matrix_sync(Cs + wm * 16 * 100 + wn * 48 + 16, c1, 100, wmma::mem_row_major);
    wmma::store_matrix_sync(Cs + wm * 16 * 100 + wn * 48 + 32, c2, 100, wmma::mem_row_major);
    __syncthreads();

    // h out (fp16), coalesced: 64 rows x 32 half2
    for (int i = t; i < 2048; i += 256) {
        int r = i >> 5, c2h = i & 31;
        int gr = row0 + r;
        if (gr < NN)
            hout[gr * 32 + c2h] =
                __floats2half2_rn(Cs[r * 100 + c2h * 2], Cs[r * 100 + c2h * 2 + 1]);
    }
    // scores straight out of the GEMM
    if (t < 64) {
        int gr = row0 + t;
        if (gr < NN) {
            g_ssrc[gr] = Cs[t * 100 + 64];
            g_sdst[gr] = Cs[t * 100 + 65];
        }
    }
}

// ---------------- GAT aggregation: warp per destination node (R6 form) -------
__global__ void __launch_bounds__(256) k_node(const __half2* __restrict__ h2,
                                              float* __restrict__ aggout,
                                              const float* __restrict__ b2,
                                              const float* __restrict__ Wl,
                                              const float* __restrict__ bl,
                                              float* __restrict__ out,
                                              int final_mode)
{
    __shared__ int   sS[8][32];
    __shared__ float sW[8][32];
    int warp = (blockIdx.x * blockDim.x + threadIdx.x) >> 5;
    int lane = threadIdx.x & 31;
    int w8   = (threadIdx.x >> 5) & 7;
    if (warp >= NN) return;
    int i = warp;
    int r0 = (i > 0) ? g_cur[i - 1] : 0;
    int r1 = g_cur[i];
    float sd = g_sdst[i];

    float ex = __expf(fminf(leaky(g_ssrc[i] + sd), 60.f));   // self loop
    float2 hs = __half22float2(h2[i * 32 + lane]);
    float ax = ex * hs.x, ay = ex * hs.y;
    float dl = 0.f;

    for (int eb = r0; eb < r1; eb += 32) {
        int idx = eb + lane;
        int   s_l = 0;
        float w_l = 0.f;
        if (idx < r1) {
            s_l = g_csrc[idx];
            w_l = __expf(fminf(leaky(g_ssrc[s_l] + sd), 60.f));
        }
        sS[w8][lane] = s_l;
        sW[w8][lane] = w_l;
        dl += w_l;
        __syncwarp();
        int n = min(32, r1 - eb);
        int j = 0;
        for (; j + 4 <= n; j += 4) {
            int   s0 = sS[w8][j],     s1 = sS[w8][j + 1];
            int   s2 = sS[w8][j + 2], s3 = sS[w8][j + 3];
            float w0 = sW[w8][j],     w1 = sW[w8][j + 1];
            float w2 = sW[w8][j + 2], w3 = sW[w8][j + 3];
            float2 f0 = __half22float2(h2[s0 * 32 + lane]);
            float2 f1 = __half22float2(h2[s1 * 32 + lane]);
            float2 f2 = __half22float2(h2[s2 * 32 + lane]);
            float2 f3 = __half22float2(h2[s3 * 32 + lane]);
            ax += w0 * f0.x + w1 * f1.x + w2 * f2.x + w3 * f3.x;
            ay += w0 * f0.y + w1 * f1.y + w2 * f2.y + w3 * f3.y;
        }
        for (; j < n; j++) {
            int   s0 = sS[w8][j];
            float w0 = sW[w8][j];
            float2 f0 = __half22float2(h2[s0 * 32 + lane]);
            ax += w0 * f0.x;
            ay += w0 * f0.y;
        }
        __syncwarp();
    }
#pragma unroll
    for (int o = 16; o; o >>= 1) dl += __shfl_xor_sync(~0u, dl, o);
    float inv = 1.f / (ex + dl + EPS);

    if (!final_mode) {
        aggout[i * 64 + lane * 2]     = ax * inv;
        aggout[i * 64 + lane * 2 + 1] = ay * inv;
    } else {
        float2 bv = *(const float2*)&b2[lane * 2];
        float2 wv = *(const float2*)&Wl[lane * 2];
        float s = (ax * inv + bv.x) * wv.x + (ay * inv + bv.y) * wv.y;
#pragma unroll
        for (int o = 16; o; o >>= 1) s += __shfl_xor_sync(~0u, s, o);
        if (!lane) out[i] = s + bl[0];
    }
}

// ---------------- launcher ---------------------------------------------------
static cudaStream_t s_csr = nullptr;
static cudaEvent_t  s_evFork = nullptr, s_evJoin = nullptr;

extern "C" void kernel_launch(void* const* d_in, const int* in_sizes, int n_in,
                              void* d_out, int out_size)
{
    const float* x     = (const float*)d_in[0];
    const int*   eidx  = (const int*)d_in[1];
    const float* W1    = (const float*)d_in[2];
    const float* as1   = (const float*)d_in[3];
    const float* ad1   = (const float*)d_in[4];
    const float* b1    = (const float*)d_in[5];
    const float* W2    = (const float*)d_in[6];
    const float* as2   = (const float*)d_in[7];
    const float* ad2   = (const float*)d_in[8];
    const float* b2    = (const float*)d_in[9];
    const float* Wl    = (const float*)d_in[10];
    const float* bl    = (const float*)d_in[11];
    float* out = (float*)d_out;

    const int4* src4 = (const int4*)eidx;
    const int4* dst4 = (const int4*)(eidx + NE);

    __half2* h_ptr = nullptr;
    float*   agg_ptr = nullptr;
    __half*  w1h = nullptr;
    __half*  w2h = nullptr;
    cudaGetSymbolAddress((void**)&h_ptr, g_h2);
    cudaGetSymbolAddress((void**)&agg_ptr, g_agg);
    cudaGetSymbolAddress((void**)&w1h, g_W1h);
    cudaGetSymbolAddress((void**)&w2h, g_W2h);

    if (!s_csr) {
        cudaStreamCreateWithFlags(&s_csr, cudaStreamNonBlocking);
        cudaEventCreateWithFlags(&s_evFork, cudaEventDisableTiming);
        cudaEventCreateWithFlags(&s_evJoin, cudaEventDisableTiming);
    }

    const int LIN_BLOCKS  = (NN + 63) / 64;          // 1563
    const int WARP_BLOCKS = (NN * 32 + 255) / 256;   // 12500
    const int E8_BLOCKS   = (NE / 8 + 255) / 256;    // 782

    // 0: weight prep (tiny)
    k_prep<<<2, 256>>>(W1, as1, ad1, W2, as2, ad2);

    // fork: CSR build runs concurrently with layer-1 linear
    cudaEventRecord(s_evFork, 0);
    cudaStreamWaitEvent(s_csr, s_evFork, 0);

    k_lin<<<LIN_BLOCKS, 256>>>(x, w1h, nullptr, 0, h_ptr);

    k_hist<<<E8_BLOCKS, 256, 0, s_csr>>>(dst4);
    k_scan<<<SCAN_NB, 1024, 0, s_csr>>>();
    k_scatter<<<E8_BLOCKS, 256, 0, s_csr>>>(src4, dst4);
    cudaEventRecord(s_evJoin, s_csr);
    cudaStreamWaitEvent(0, s_evJoin, 0);

    // layer-1 aggregation
    k_node<<<WARP_BLOCKS, 256>>>(h_ptr, agg_ptr, nullptr, nullptr, nullptr, nullptr, 0);
    // layer-2 linear (input = tanh(agg1 + b1))
    k_lin<<<LIN_BLOCKS, 256>>>(agg_ptr, w2h, b1, 1, h_ptr);
    // layer-2 aggregation + fused readout
    k_node<<<WARP_BLOCKS, 256>>>(h_ptr, nullptr, b2, Wl, bl, out, 1);
}

// round 12
// speedup vs baseline: 1.1995x; 1.1563x over previous
#include <cuda_runtime.h>
#include <cuda_bf16.h>
#include <cuda_fp16.h>
#include <mma.h>
#include <cstdint>

using namespace nvcuda;

// Problem constants (fixed-shape problem)
#define NN 100000
#define NE 1600000
#define SCAN_NB 98                      // ceil(100000/1024)
#define EPS 1e-16f

// ---------------- scratch (device globals; no allocation allowed) ------------
__device__ __half2 g_h2a[NN * 32];  // layer-1 features (fp16)
__device__ __half2 g_h2b[NN * 32];  // layer-2 features (fp16)
__device__ float g_ssrc[NN];        // layer-1 scores
__device__ float g_sdst[NN];
__device__ float g_ssrc2[NN];       // layer-2 scores
__device__ float g_sdst2[NN];
__device__ int   g_deg[NN];         // zero-init at load; re-zeroed by k_scan each run
__device__ int   g_cur[NN];         // exclusive prefix -> after scatter: inclusive
__device__ int   g_csrc[NE];
__device__ int   g_bsums[128];
__device__ int   g_done;
__device__ int   g_epoch;
__device__ __half g_W1h[64 * 96];   // [W | W@a_src | W@a_dst | 0...] fp16
__device__ __half g_W2h[64 * 96];

__device__ __forceinline__ float leaky(float v) {
    return fmaxf(v, 0.2f * v);   // NEG_SLOPE = 0.2
}

__device__ __forceinline__ float tanh_fast(float v) {
    asm("tanh.approx.f32 %0, %0;" : "+f"(v));
    return v;
}

// ---------------- weight prep: build 64x96 fp16 tiles ------------------------
__global__ void k_prep(const float* __restrict__ W1, const float* __restrict__ as1,
                       const float* __restrict__ ad1,
                       const float* __restrict__ W2, const float* __restrict__ as2,
                       const float* __restrict__ ad2)
{
    const float* W  = blockIdx.x ? W2 : W1;
    const float* as = blockIdx.x ? as2 : as1;
    const float* ad = blockIdx.x ? ad2 : ad1;
    __half* Wh = blockIdx.x ? g_W2h : g_W1h;
    int t = threadIdx.x;
    for (int i = t; i < 64 * 96; i += 256) Wh[i] = __float2half(0.f);
    __syncthreads();
    for (int i = t; i < 4096; i += 256) {
        int k = i >> 6, j = i & 63;
        Wh[k * 96 + j] = __float2half(W[i]);
    }
    if (t < 64) {
        float ds = 0.f, dd = 0.f;
        for (int j = 0; j < 64; j++) {
            float w = W[t * 64 + j];
            ds += w * as[j];
            dd += w * ad[j];
        }
        Wh[t * 96 + 64] = __float2half(ds);
        Wh[t * 96 + 65] = __float2half(dd);
    }
}

// ---------------- histogram of dst (8 independent chains / thread) ----------
__global__ void k_hist(const int4* __restrict__ dst4) {
    const int Q = NE / 8;
    int t = blockIdx.x * blockDim.x + threadIdx.x;
    if (t < Q) {
        int4 d0 = dst4[t];
        int4 d1 = dst4[t + Q];
        atomicAdd(&g_deg[d0.x], 1);
        atomicAdd(&g_deg[d0.y], 1);
        atomicAdd(&g_deg[d0.z], 1);
        atomicAdd(&g_deg[d0.w], 1);
        atomicAdd(&g_deg[d1.x], 1);
        atomicAdd(&g_deg[d1.y], 1);
        atomicAdd(&g_deg[d1.z], 1);
        atomicAdd(&g_deg[d1.w], 1);
    }
}

// ---------------- single-kernel exclusive scan of deg -> g_cur ---------------
__global__ void __launch_bounds__(1024) k_scan() {
    __shared__ int swarp[32];
    __shared__ int sboff[128];
    int t = threadIdx.x, b = blockIdx.x;
    int lane = t & 31, wid = t >> 5;
    int idx = b * 1024 + t;

    int e0 = 0;
    if (t == 0) e0 = *(volatile int*)&g_epoch;

    int v = (idx < NN) ? g_deg[idx] : 0;
    if (idx < NN) g_deg[idx] = 0;

    int x = v;
#pragma unroll
    for (int off = 1; off < 32; off <<= 1) {
        int y = __shfl_up_sync(~0u, x, off);
        if (lane >= off) x += y;
    }
    if (lane == 31) swarp[wid] = x;
    __syncthreads();
    if (wid == 0) {
        int s = swarp[lane];
#pragma unroll
        for (int off = 1; off < 32; off <<= 1) {
            int y = __shfl_up_sync(~0u, s, off);
            if (lane >= off) s += y;
        }
        swarp[lane] = s;
    }
    __syncthreads();
    int incl = x + (wid ? swarp[wid - 1] : 0);
    int ex = incl - v;
    int total = swarp[31];

    if (t == 0) {
        g_bsums[b] = total;
        __threadfence();
        int r = atomicAdd(&g_done, 1);
        if (r == SCAN_NB - 1) {
            g_done = 0;
            __threadfence();
            atomicAdd(&g_epoch, 1);
        }
        while (*(volatile int*)&g_epoch == e0) { }
    }
    __syncthreads();

    if (t < 128) sboff[t] = (t < SCAN_NB) ? g_bsums[t] : 0;
    __syncthreads();
    for (int off = 1; off < 128; off <<= 1) {
        int y = 0;
        if (t < 128) { y = sboff[t]; if (t >= off) y += sboff[t - off]; }
        __syncthreads();
        if (t < 128) sboff[t] = y;
        __syncthreads();
    }
    int boff = b ? sboff[b - 1] : 0;
    if (idx < NN) g_cur[idx] = ex + boff;
}

// ---------------- CSR scatter (8 independent chains / thread) ----------------
__global__ void k_scatter(const int4* __restrict__ src4, const int4* __restrict__ dst4) {
    const int Q = NE / 8;
    int t = blockIdx.x * blockDim.x + threadIdx.x;
    if (t < Q) {
        int4 s0 = src4[t];
        int4 d0 = dst4[t];
        int4 s1 = src4[t + Q];
        int4 d1 = dst4[t + Q];
        g_csrc[atomicAdd(&g_cur[d0.x], 1)] = s0.x;
        g_csrc[atomicAdd(&g_cur[d0.y], 1)] = s0.y;
        g_csrc[atomicAdd(&g_cur[d0.z], 1)] = s0.z;
        g_csrc[atomicAdd(&g_cur[d0.w], 1)] = s0.w;
        g_csrc[atomicAdd(&g_cur[d1.x], 1)] = s1.x;
        g_csrc[atomicAdd(&g_cur[d1.y], 1)] = s1.y;
        g_csrc[atomicAdd(&g_cur[d1.z], 1)] = s1.z;
        g_csrc[atomicAdd(&g_cur[d1.w], 1)] = s1.w;
    }
}

// ---------------- layer-1 linear: C[64x96] = x[64x64] @ W1h[64x96] -----------
__global__ void __launch_bounds__(256) k_lin(
    const float* __restrict__ xin, const __half* __restrict__ Wg,
    __half2* __restrict__ hout)
{
    __shared__ __half Xh[64 * 72];
    __shared__ __half Wh[64 * 96];
    __shared__ float  Cs[64 * 100];
    int t = threadIdx.x;
    int row0 = blockIdx.x * 64;

    {
        const int4* Wsrc = (const int4*)Wg;
        int4* Wdst = (int4*)Wh;
        for (int i = t; i < 768; i += 256) Wdst[i] = Wsrc[i];
    }
    for (int i = t; i < 4096; i += 256) {
        int r = i >> 6, c = i & 63;
        float v = 0.f;
        int gr = row0 + r;
        if (gr < NN) v = xin[gr * 64 + c];
        Xh[r * 72 + c] = __float2half(v);
    }
    __syncthreads();

    int w  = t >> 5;
    int wm = w & 3;
    int wn = w >> 2;
    wmma::fragment<wmma::accumulator, 16, 16, 16, float> c0, c1, c2;
    wmma::fill_fragment(c0, 0.f);
    wmma::fill_fragment(c1, 0.f);
    wmma::fill_fragment(c2, 0.f);
#pragma unroll
    for (int k0 = 0; k0 < 64; k0 += 16) {
        wmma::fragment<wmma::matrix_a, 16, 16, 16, __half, wmma::row_major> a;
        wmma::fragment<wmma::matrix_b, 16, 16, 16, __half, wmma::row_major> b0, b1, b2;
        wmma::load_matrix_sync(a, Xh + wm * 16 * 72 + k0, 72);
        wmma::load_matrix_sync(b0, Wh + k0 * 96 + wn * 48, 96);
        wmma::load_matrix_sync(b1, Wh + k0 * 96 + wn * 48 + 16, 96);
        wmma::load_matrix_sync(b2, Wh + k0 * 96 + wn * 48 + 32, 96);
        wmma::mma_sync(c0, a, b0, c0);
        wmma::mma_sync(c1, a, b1, c1);
        wmma::mma_sync(c2, a, b2, c2);
    }
    wmma::store_matrix_sync(Cs + wm * 16 * 100 + wn * 48,      c0, 100, wmma::mem_row_major);
    wmma::store_matrix_sync(Cs + wm * 16 * 100 + wn * 48 + 16, c1, 100, wmma::mem_row_major);
    wmma::store_matrix_sync(Cs + wm * 16 * 100 + wn * 48 + 32, c2, 100, wmma::mem_row_major);
    __syncthreads();

    for (int i = t; i < 2048; i += 256) {
        int r = i >> 5, c2h = i & 31;
        int gr = row0 + r;
        if (gr < NN)
            hout[gr * 32 + c2h] =
                __floats2half2_rn(Cs[r * 100 + c2h * 2], Cs[r * 100 + c2h * 2 + 1]);
    }
    if (t < 64) {
        int gr = row0 + t;
        if (gr < NN) {
            g_ssrc[gr] = Cs[t * 100 + 64];
            g_sdst[gr] = Cs[t * 100 + 65];
        }
    }
}

// ---------------- FUSED: layer-1 aggregation + layer-2 linear ----------------
// 512 threads = 16 warps, warp per node -> 16-node tile. agg tile stays in
// smem; warps 0-5 run the 16x96 wmma GEMM with W2h; outputs go to the B
// buffers (double-buffered vs the layer-1 arrays being gathered concurrently).
__global__ void __launch_bounds__(512) k_node_lin(
    const __half2* __restrict__ h2, const float* __restrict__ b1)
{
    __shared__ int    sS[16][32];
    __shared__ float  sW[16][32];
    __shared__ __half Ah[16 * 72];       // agg tile (fp16, post-activation)
    __shared__ __half Ws[64 * 96];
    __shared__ float  Cs[16 * 100];
    int t = threadIdx.x;
    int w = t >> 5;
    int lane = t & 31;
    int row0 = blockIdx.x * 16;
    int i = row0 + w;                     // NN = 6250*16, always valid

    // stage W2h while aggregating is set up
    {
        const int4* Wsrc = (const int4*)g_W2h;
        int4* Wdst = (int4*)Ws;
        for (int k = t; k < 768; k += 512) Wdst[k] = Wsrc[k];
    }

    int r0 = (i > 0) ? g_cur[i - 1] : 0;
    int r1 = g_cur[i];
    float sd = g_sdst[i];

    float ex = __expf(fminf(leaky(g_ssrc[i] + sd), 60.f));   // self loop
    float2 hs = __half22float2(h2[i * 32 + lane]);
    float ax = ex * hs.x, ay = ex * hs.y;
    float dl = 0.f;

    for (int eb = r0; eb < r1; eb += 32) {
        int idx = eb + lane;
        int   s_l = 0;
        float w_l = 0.f;
        if (idx < r1) {
            s_l = g_csrc[idx];
            w_l = __expf(fminf(leaky(g_ssrc[s_l] + sd), 60.f));
        }
        sS[w][lane] = s_l;
        sW[w][lane] = w_l;
        dl += w_l;
        __syncwarp();
        int n = min(32, r1 - eb);
        int j = 0;
        for (; j + 4 <= n; j += 4) {
            int   s0 = sS[w][j],     s1 = sS[w][j + 1];
            int   s2 = sS[w][j + 2], s3 = sS[w][j + 3];
            float w0 = sW[w][j],     w1 = sW[w][j + 1];
            float w2 = sW[w][j + 2], w3 = sW[w][j + 3];
            float2 f0 = __half22float2(h2[s0 * 32 + lane]);
            float2 f1 = __half22float2(h2[s1 * 32 + lane]);
            float2 f2 = __half22float2(h2[s2 * 32 + lane]);
            float2 f3 = __half22float2(h2[s3 * 32 + lane]);
            ax += w0 * f0.x + w1 * f1.x + w2 * f2.x + w3 * f3.x;
            ay += w0 * f0.y + w1 * f1.y + w2 * f2.y + w3 * f3.y;
        }
        for (; j < n; j++) {
            int   s0 = sS[w][j];
            float w0 = sW[w][j];
            float2 f0 = __half22float2(h2[s0 * 32 + lane]);
            ax += w0 * f0.x;
            ay += w0 * f0.y;
        }
        __syncwarp();
    }
#pragma unroll
    for (int o = 16; o; o >>= 1) dl += __shfl_xor_sync(~0u, dl, o);
    float inv = 1.f / (ex + dl + EPS);

    // layer-2 input: tanh(agg + b1), fp16 into smem tile
    {
        int c = lane * 2;
        float v0 = tanh_fast(ax * inv + b1[c]);
        float v1 = tanh_fast(ay * inv + b1[c + 1]);
        *(__half2*)&Ah[w * 72 + c] = __floats2half2_rn(v0, v1);
    }
    __syncthreads();

    // GEMM 16x96: warps 0-5, 16-col chunks
    if (w < 6) {
        wmma::fragment<wmma::accumulator, 16, 16, 16, float> cc;
        wmma::fill_fragment(cc, 0.f);
#pragma unroll
        for (int k0 = 0; k0 < 64; k0 += 16) {
            wmma::fragment<wmma::matrix_a, 16, 16, 16, __half, wmma::row_major> a;
            wmma::fragment<wmma::matrix_b, 16, 16, 16, __half, wmma::row_major> bb;
            wmma::load_matrix_sync(a, Ah + k0, 72);
            wmma::load_matrix_sync(bb, Ws + k0 * 96 + w * 16, 96);
            wmma::mma_sync(cc, a, bb, cc);
        }
        wmma::store_matrix_sync(Cs + w * 16, cc, 100, wmma::mem_row_major);
    }
    __syncthreads();

    // write layer-2 h (fp16) + scores to B buffers
    {
        int r = t >> 5, c2h = t & 31;     // 512 threads = 16 rows x 32 half2
        g_h2b[(row0 + r) * 32 + c2h] =
            __floats2half2_rn(Cs[r * 100 + c2h * 2], Cs[r * 100 + c2h * 2 + 1]);
    }
    if (t < 16) {
        g_ssrc2[row0 + t] = Cs[t * 100 + 64];
        g_sdst2[row0 + t] = Cs[t * 100 + 65];
    }
}

// ---------------- layer-2 aggregation + fused readout ------------------------
__global__ void __launch_bounds__(256) k_node2(const __half2* __restrict__ h2,
                                               const float* __restrict__ b2,
                                               const float* __restrict__ Wl,
                                               const float* __restrict__ bl,
                                               float* __restrict__ out)
{
    __shared__ int   sS[8][32];
    __shared__ float sW[8][32];
    int warp = (blockIdx.x * blockDim.x + threadIdx.x) >> 5;
    int lane = threadIdx.x & 31;
    int w8   = (threadIdx.x >> 5) & 7;
    if (warp >= NN) return;
    int i = warp;
    int r0 = (i > 0) ? g_cur[i - 1] : 0;
    int r1 = g_cur[i];
    float sd = g_sdst2[i];

    float ex = __expf(fminf(leaky(g_ssrc2[i] + sd), 60.f));
    float2 hs = __half22float2(h2[i * 32 + lane]);
    float ax = ex * hs.x, ay = ex * hs.y;
    float dl = 0.f;

    for (int eb = r0; eb < r1; eb += 32) {
        int idx = eb + lane;
        int   s_l = 0;
        float w_l = 0.f;
        if (idx < r1) {
            s_l = g_csrc[idx];
            w_l = __expf(fminf(leaky(g_ssrc2[s_l] + sd), 60.f));
        }
        sS[w8][lane] = s_l;
        sW[w8][lane] = w_l;
        dl += w_l;
        __syncwarp();
        int n = min(32, r1 - eb);
        int j = 0;
        for (; j + 4 <= n; j += 4) {
            int   s0 = sS[w8][j],     s1 = sS[w8][j + 1];
            int   s2 = sS[w8][j + 2], s3 = sS[w8][j + 3];
            float w0 = sW[w8][j],     w1 = sW[w8][j + 1];
            float w2 = sW[w8][j + 2], w3 = sW[w8][j + 3];
            float2 f0 = __half22float2(h2[s0 * 32 + lane]);
            float2 f1 = __half22float2(h2[s1 * 32 + lane]);
            float2 f2 = __half22float2(h2[s2 * 32 + lane]);
            float2 f3 = __half22float2(h2[s3 * 32 + lane]);
            ax += w0 * f0.x + w1 * f1.x + w2 * f2.x + w3 * f3.x;
            ay += w0 * f0.y + w1 * f1.y + w2 * f2.y + w3 * f3.y;
        }
        for (; j < n; j++) {
            int   s0 = sS[w8][j];
            float w0 = sW[w8][j];
            float2 f0 = __half22float2(h2[s0 * 32 + lane]);
            ax += w0 * f0.x;
            ay += w0 * f0.y;
        }
        __syncwarp();
    }
#pragma unroll
    for (int o = 16; o; o >>= 1) dl += __shfl_xor_sync(~0u, dl, o);
    float inv = 1.f / (ex + dl + EPS);

    float2 bv = *(const float2*)&b2[lane * 2];
    float2 wv = *(const float2*)&Wl[lane * 2];
    float s = (ax * inv + bv.x) * wv.x + (ay * inv + bv.y) * wv.y;
#pragma unroll
    for (int o = 16; o; o >>= 1) s += __shfl_xor_sync(~0u, s, o);
    if (!lane) out[i] = s + bl[0];
}

// ---------------- launcher ---------------------------------------------------
static cudaStream_t s_csr = nullptr;
static cudaEvent_t  s_evFork = nullptr, s_evJoin = nullptr;

extern "C" void kernel_launch(void* const* d_in, const int* in_sizes, int n_in,
                              void* d_out, int out_size)
{
    const float* x     = (const float*)d_in[0];
    const int*   eidx  = (const int*)d_in[1];
    const float* W1    = (const float*)d_in[2];
    const float* as1   = (const float*)d_in[3];
    const float* ad1   = (const float*)d_in[4];
    const float* b1    = (const float*)d_in[5];
    const float* W2    = (const float*)d_in[6];
    const float* as2   = (const float*)d_in[7];
    const float* ad2   = (const float*)d_in[8];
    const float* b2    = (const float*)d_in[9];
    const float* Wl    = (const float*)d_in[10];
    const float* bl    = (const float*)d_in[11];
    float* out = (float*)d_out;

    const int4* src4 = (const int4*)eidx;
    const int4* dst4 = (const int4*)(eidx + NE);

    __half2* ha = nullptr;
    __half2* hb = nullptr;
    __half*  w1h = nullptr;
    cudaGetSymbolAddress((void**)&ha, g_h2a);
    cudaGetSymbolAddress((void**)&hb, g_h2b);
    cudaGetSymbolAddress((void**)&w1h, g_W1h);

    if (!s_csr) {
        cudaStreamCreateWithFlags(&s_csr, cudaStreamNonBlocking);
        cudaEventCreateWithFlags(&s_evFork, cudaEventDisableTiming);
        cudaEventCreateWithFlags(&s_evJoin, cudaEventDisableTiming);
    }

    const int LIN_BLOCKS  = (NN + 63) / 64;          // 1563
    const int FUSE_BLOCKS = NN / 16;                 // 6250
    const int WARP_BLOCKS = (NN * 32 + 255) / 256;   // 12500
    const int E8_BLOCKS   = (NE / 8 + 255) / 256;    // 782

    // weight prep (tiny)
    k_prep<<<2, 256>>>(W1, as1, ad1, W2, as2, ad2);

    // fork: CSR build runs concurrently with layer-1 linear
    cudaEventRecord(s_evFork, 0);
    cudaStreamWaitEvent(s_csr, s_evFork, 0);

    k_lin<<<LIN_BLOCKS, 256>>>(x, w1h, ha);

    k_hist<<<E8_BLOCKS, 256, 0, s_csr>>>(dst4);
    k_scan<<<SCAN_NB, 1024, 0, s_csr>>>();
    k_scatter<<<E8_BLOCKS, 256, 0, s_csr>>>(src4, dst4);
    cudaEventRecord(s_evJoin, s_csr);
    cudaStreamWaitEvent(0, s_evJoin, 0);

    // layer-1 aggregation + layer-2 linear (fused)
    k_node_lin<<<FUSE_BLOCKS, 512>>>(ha, b1);
    // layer-2 aggregation + fused readout
    k_node2<<<WARP_BLOCKS, 256>>>(hb, b2, Wl, bl, out);
}

// round 14
// speedup vs baseline: 1.2002x; 1.0006x over previous
#include <cuda_runtime.h>
#include <cuda_bf16.h>
#include <cuda_fp16.h>
#include <mma.h>
#include <cstdint>

using namespace nvcuda;

// Problem constants (fixed-shape problem)
#define NN 100000
#define NE 1600000
#define SCAN_NB 98                      // ceil(100000/1024)
#define EPS 1e-16f

// ---------------- scratch (device globals; no allocation allowed) ------------
__device__ __half2 g_h2a[NN * 32];  // layer-1 features (fp16)
__device__ __half2 g_h2b[NN * 32];  // layer-2 features (fp16)
__device__ float g_ssrc[NN];        // layer-1 scores
__device__ float g_sdst[NN];
__device__ float g_ssrc2[NN];       // layer-2 scores
__device__ float g_sdst2[NN];
__device__ int   g_deg[NN];         // zero-init at load; re-zeroed by k_scan each run
__device__ int   g_cur[NN];         // exclusive prefix -> after scatter: inclusive
__device__ int   g_csrc[NE];
__device__ int   g_bsums[128];
__device__ int   g_done;
__device__ int   g_epoch;
__device__ __half g_W1h[64 * 96];   // [W | W@a_src | W@a_dst | 0...] fp16
__device__ __half g_W2h[64 * 96];

__device__ __forceinline__ float leaky(float v) {
    return fmaxf(v, 0.2f * v);   // NEG_SLOPE = 0.2
}

__device__ __forceinline__ float tanh_fast(float v) {
    asm("tanh.approx.f32 %0, %0;" : "+f"(v));
    return v;
}

// ---------------- weight prep: build 64x96 fp16 tiles ------------------------
__global__ void k_prep(const float* __restrict__ W1, const float* __restrict__ as1,
                       const float* __restrict__ ad1,
                       const float* __restrict__ W2, const float* __restrict__ as2,
                       const float* __restrict__ ad2)
{
    const float* W  = blockIdx.x ? W2 : W1;
    const float* as = blockIdx.x ? as2 : as1;
    const float* ad = blockIdx.x ? ad2 : ad1;
    __half* Wh = blockIdx.x ? g_W2h : g_W1h;
    int t = threadIdx.x;
    for (int i = t; i < 64 * 96; i += 256) Wh[i] = __float2half(0.f);
    __syncthreads();
    for (int i = t; i < 4096; i += 256) {
        int k = i >> 6, j = i & 63;
        Wh[k * 96 + j] = __float2half(W[i]);
    }
    if (t < 64) {
        float ds = 0.f, dd = 0.f;
        for (int j = 0; j < 64; j++) {
            float w = W[t * 64 + j];
            ds += w * as[j];
            dd += w * ad[j];
        }
        Wh[t * 96 + 64] = __float2half(ds);
        Wh[t * 96 + 65] = __float2half(dd);
    }
}

// ---------------- histogram of dst (8 independent chains / thread) ----------
__global__ void k_hist(const int4* __restrict__ dst4) {
    const int Q = NE / 8;
    int t = blockIdx.x * blockDim.x + threadIdx.x;
    if (t < Q) {
        int4 d0 = dst4[t];
        int4 d1 = dst4[t + Q];
        atomicAdd(&g_deg[d0.x], 1);
        atomicAdd(&g_deg[d0.y], 1);
        atomicAdd(&g_deg[d0.z], 1);
        atomicAdd(&g_deg[d0.w], 1);
        atomicAdd(&g_deg[d1.x], 1);
        atomicAdd(&g_deg[d1.y], 1);
        atomicAdd(&g_deg[d1.z], 1);
        atomicAdd(&g_deg[d1.w], 1);
    }
}

// ---------------- single-kernel exclusive scan of deg -> g_cur ---------------
__global__ void __launch_bounds__(1024) k_scan() {
    __shared__ int swarp[32];
    __shared__ int sboff[128];
    int t = threadIdx.x, b = blockIdx.x;
    int lane = t & 31, wid = t >> 5;
    int idx = b * 1024 + t;

    int e0 = 0;
    if (t == 0) e0 = *(volatile int*)&g_epoch;

    int v = (idx < NN) ? g_deg[idx] : 0;
    if (idx < NN) g_deg[idx] = 0;

    int x = v;
#pragma unroll
    for (int off = 1; off < 32; off <<= 1) {
        int y = __shfl_up_sync(~0u, x, off);
        if (lane >= off) x += y;
    }
    if (lane == 31) swarp[wid] = x;
    __syncthreads();
    if (wid == 0) {
        int s = swarp[lane];
#pragma unroll
        for (int off = 1; off < 32; off <<= 1) {
            int y = __shfl_up_sync(~0u, s, off);
            if (lane >= off) s += y;
        }
        swarp[lane] = s;
    }
    __syncthreads();
    int incl = x + (wid ? swarp[wid - 1] : 0);
    int ex = incl - v;
    int total = swarp[31];

    if (t == 0) {
        g_bsums[b] = total;
        __threadfence();
        int r = atomicAdd(&g_done, 1);
        if (r == SCAN_NB - 1) {
            g_done = 0;
            __threadfence();
            atomicAdd(&g_epoch, 1);
        }
        while (*(volatile int*)&g_epoch == e0) { }
    }
    __syncthreads();

    if (t < 128) sboff[t] = (t < SCAN_NB) ? g_bsums[t] : 0;
    __syncthreads();
    for (int off = 1; off < 128; off <<= 1) {
        int y = 0;
        if (t < 128) { y = sboff[t]; if (t >= off) y += sboff[t - off]; }
        __syncthreads();
        if (t < 128) sboff[t] = y;
        __syncthreads();
    }
    int boff = b ? sboff[b - 1] : 0;
    if (idx < NN) g_cur[idx] = ex + boff;
}

// ---------------- CSR scatter (8 independent chains / thread) ----------------
__global__ void k_scatter(const int4* __restrict__ src4, const int4* __restrict__ dst4) {
    const int Q = NE / 8;
    int t = blockIdx.x * blockDim.x + threadIdx.x;
    if (t < Q) {
        int4 s0 = src4[t];
        int4 d0 = dst4[t];
        int4 s1 = src4[t + Q];
        int4 d1 = dst4[t + Q];
        g_csrc[atomicAdd(&g_cur[d0.x], 1)] = s0.x;
        g_csrc[atomicAdd(&g_cur[d0.y], 1)] = s0.y;
        g_csrc[atomicAdd(&g_cur[d0.z], 1)] = s0.z;
        g_csrc[atomicAdd(&g_cur[d0.w], 1)] = s0.w;
        g_csrc[atomicAdd(&g_cur[d1.x], 1)] = s1.x;
        g_csrc[atomicAdd(&g_cur[d1.y], 1)] = s1.y;
        g_csrc[atomicAdd(&g_cur[d1.z], 1)] = s1.z;
        g_csrc[atomicAdd(&g_cur[d1.w], 1)] = s1.w;
    }
}

// ---------------- layer-1 linear: C[64x96] = x[64x64] @ W1h[64x96] -----------
__global__ void __launch_bounds__(256) k_lin(
    const float* __restrict__ xin, const __half* __restrict__ Wg,
    __half2* __restrict__ hout)
{
    __shared__ __half Xh[64 * 72];
    __shared__ __half Wh[64 * 96];
    __shared__ float  Cs[64 * 100];
    int t = threadIdx.x;
    int row0 = blockIdx.x * 64;

    {
        const int4* Wsrc = (const int4*)Wg;
        int4* Wdst = (int4*)Wh;
        for (int i = t; i < 768; i += 256) Wdst[i] = Wsrc[i];
    }
    for (int i = t; i < 4096; i += 256) {
        int r = i >> 6, c = i & 63;
        float v = 0.f;
        int gr = row0 + r;
        if (gr < NN) v = xin[gr * 64 + c];
        Xh[r * 72 + c] = __float2half(v);
    }
    __syncthreads();

    int w  = t >> 5;
    int wm = w & 3;
    int wn = w >> 2;
    wmma::fragment<wmma::accumulator, 16, 16, 16, float> c0, c1, c2;
    wmma::fill_fragment(c0, 0.f);
    wmma::fill_fragment(c1, 0.f);
    wmma::fill_fragment(c2, 0.f);
#pragma unroll
    for (int k0 = 0; k0 < 64; k0 += 16) {
        wmma::fragment<wmma::matrix_a, 16, 16, 16, __half, wmma::row_major> a;
        wmma::fragment<wmma::matrix_b, 16, 16, 16, __half, wmma::row_major> b0, b1, b2;
        wmma::load_matrix_sync(a, Xh + wm * 16 * 72 + k0, 72);
        wmma::load_matrix_sync(b0, Wh + k0 * 96 + wn * 48, 96);
        wmma::load_matrix_sync(b1, Wh + k0 * 96 + wn * 48 + 16, 96);
        wmma::load_matrix_sync(b2, Wh + k0 * 96 + wn * 48 + 32, 96);
        wmma::mma_sync(c0, a, b0, c0);
        wmma::mma_sync(c1, a, b1, c1);
        wmma::mma_sync(c2, a, b2, c2);
    }
    wmma::store_matrix_sync(Cs + wm * 16 * 100 + wn * 48,      c0, 100, wmma::mem_row_major);
    wmma::store_matrix_sync(Cs + wm * 16 * 100 + wn * 48 + 16, c1, 100, wmma::mem_row_major);
    wmma::store_matrix_sync(Cs + wm * 16 * 100 + wn * 48 + 32, c2, 100, wmma::mem_row_major);
    __syncthreads();

    for (int i = t; i < 2048; i += 256) {
        int r = i >> 5, c2h = i & 31;
        int gr = row0 + r;
        if (gr < NN)
            hout[gr * 32 + c2h] =
                __floats2half2_rn(Cs[r * 100 + c2h * 2], Cs[r * 100 + c2h * 2 + 1]);
    }
    if (t < 64) {
        int gr = row0 + t;
        if (gr < NN) {
            g_ssrc[gr] = Cs[t * 100 + 64];
            g_sdst[gr] = Cs[t * 100 + 65];
        }
    }
}

// ---------------- shared gather core: warp-per-node, 2 edges/iter ------------
// Lanes 0-15 gather even edges (uint2 = 4 feats/lane), lanes 16-31 odd edges.
// Accumulators per lane: feats sub*4 .. sub*4+3. Final shfl_xor(16) merges.
// Returns via refs; sP is per-warp staging of packed (s, w_bits).
struct GatherOut { float a0, a1, a2, a3, inv; };

__device__ __forceinline__ GatherOut gather_node(
    const __half2* __restrict__ h2, const float* __restrict__ ssrc,
    float sd, float ex, int i, int r0, int r1,
    int2* sP /*[32] for this warp*/, int lane)
{
    int half = lane >> 4;
    int sub  = lane & 15;
    float a0 = 0.f, a1 = 0.f, a2 = 0.f, a3 = 0.f;
    if (half == 0) {
        uint2 sv = __ldg((const uint2*)(h2 + i * 32) + sub);
        float2 s0 = __half22float2(*(__half2*)&sv.x);
        float2 s1 = __half22float2(*(__half2*)&sv.y);
        a0 = ex * s0.x; a1 = ex * s0.y; a2 = ex * s1.x; a3 = ex * s1.y;
    }
    float dl = 0.f;

    for (int eb = r0; eb < r1; eb += 32) {
        int idx = eb + lane;
        int   s_l = 0;
        float w_l = 0.f;
        if (idx < r1) {
            s_l = __ldg(&g_csrc[idx]);
            w_l = __expf(fminf(leaky(ssrc[s_l] + sd), 60.f));
        }
        sP[lane] = make_int2(s_l, __float_as_int(w_l));
        dl += w_l;
        __syncwarp();
        int n  = min(32, r1 - eb);
        int it = (n + 1) >> 1;           // edge pairs
        int j = 0;
        for (; j + 4 <= it; j += 4) {
            int2 p0 = sP[2 * j + half];
            int2 p1 = sP[2 * (j + 1) + half];
            int2 p2 = sP[2 * (j + 2) + half];
            int2 p3 = sP[2 * (j + 3) + half];
            uint2 r0v = __ldg((const uint2*)(h2 + p0.x * 32) + sub);
            uint2 r1v = __ldg((const uint2*)(h2 + p1.x * 32) + sub);
            uint2 r2v = __ldg((const uint2*)(h2 + p2.x * 32) + sub);
            uint2 r3v = __ldg((const uint2*)(h2 + p3.x * 32) + sub);
            float w0 = __int_as_float(p0.y), w1 = __int_as_float(p1.y);
            float w2 = __int_as_float(p2.y), w3 = __int_as_float(p3.y);
            float2 f00 = __half22float2(*(__half2*)&r0v.x);
            float2 f01 = __half22float2(*(__half2*)&r0v.y);
            float2 f10 = __half22float2(*(__half2*)&r1v.x);
            float2 f11 = __half22float2(*(__half2*)&r1v.y);
            float2 f20 = __half22float2(*(__half2*)&r2v.x);
            float2 f21 = __half22float2(*(__half2*)&r2v.y);
            float2 f30 = __half22float2(*(__half2*)&r3v.x);
            float2 f31 = __half22float2(*(__half2*)&r3v.y);
            a0 += w0 * f00.x + w1 * f10.x + w2 * f20.x + w3 * f30.x;
            a1 += w0 * f00.y + w1 * f10.y + w2 * f20.y + w3 * f30.y;
            a2 += w0 * f01.x + w1 * f11.x + w2 * f21.x + w3 * f31.x;
            a3 += w0 * f01.y + w1 * f11.y + w2 * f21.y + w3 * f31.y;
        }
        for (; j < it; j++) {
            int2 p0 = sP[2 * j + half];
            float w0 = __int_as_float(p0.y);
            uint2 rv = __ldg((const uint2*)(h2 + p0.x * 32) + sub);
            float2 f0 = __half22float2(*(__half2*)&rv.x);
            float2 f1 = __half22float2(*(__half2*)&rv.y);
            a0 += w0 * f0.x;
            a1 += w0 * f0.y;
            a2 += w0 * f1.x;
            a3 += w0 * f1.y;
        }
        __syncwarp();
    }
    // merge the two edge-halves (both halves end with the full sum)
    a0 += __shfl_xor_sync(~0u, a0, 16);
    a1 += __shfl_xor_sync(~0u, a1, 16);
    a2 += __shfl_xor_sync(~0u, a2, 16);
    a3 += __shfl_xor_sync(~0u, a3, 16);
#pragma unroll
    for (int o = 16; o; o >>= 1) dl += __shfl_xor_sync(~0u, dl, o);
    GatherOut g;
    g.a0 = a0; g.a1 = a1; g.a2 = a2; g.a3 = a3;
    g.inv = 1.f / (ex + dl + EPS);
    return g;
}

// ---------------- FUSED: layer-1 aggregation + layer-2 linear ----------------
__global__ void __launch_bounds__(512) k_node_lin(
    const __half2* __restrict__ h2, const float* __restrict__ b1)
{
    __shared__ int2   sP[16][32];
    __shared__ __half Ah[16 * 72];       // agg tile (fp16, post-activation)
    __shared__ __half Ws[64 * 96];
    __shared__ float  Cs[16 * 100];
    int t = threadIdx.x;
    int w = t >> 5;
    int lane = t & 31;
    int row0 = blockIdx.x * 16;
    int i = row0 + w;                     // NN = 6250*16, always valid

    {
        const int4* Wsrc = (const int4*)g_W2h;
        int4* Wdst = (int4*)Ws;
        for (int k = t; k < 768; k += 512) Wdst[k] = Wsrc[k];
    }

    int r0 = (i > 0) ? g_cur[i - 1] : 0;
    int r1 = g_cur[i];
    float sd = g_sdst[i];
    float ex = __expf(fminf(leaky(g_ssrc[i] + sd), 60.f));

    GatherOut g = gather_node(h2, g_ssrc, sd, ex, i, r0, r1, sP[w], lane);

    // layer-2 input: tanh(agg + b1), fp16 into smem tile (lanes 0-15 write)
    if (lane < 16) {
        int c = lane * 4;
        float v0 = tanh_fast(g.a0 * g.inv + b1[c]);
        float v1 = tanh_fast(g.a1 * g.inv + b1[c + 1]);
        float v2 = tanh_fast(g.a2 * g.inv + b1[c + 2]);
        float v3 = tanh_fast(g.a3 * g.inv + b1[c + 3]);
        *(__half2*)&Ah[w * 72 + c]     = __floats2half2_rn(v0, v1);
        *(__half2*)&Ah[w * 72 + c + 2] = __floats2half2_rn(v2, v3);
    }
    __syncthreads();

    // GEMM 16x96: warps 0-5, 16-col chunks
    if (w < 6) {
        wmma::fragment<wmma::accumulator, 16, 16, 16, float> cc;
        wmma::fill_fragment(cc, 0.f);
#pragma unroll
        for (int k0 = 0; k0 < 64; k0 += 16) {
            wmma::fragment<wmma::matrix_a, 16, 16, 16, __half, wmma::row_major> a;
            wmma::fragment<wmma::matrix_b, 16, 16, 16, __half, wmma::row_major> bb;
            wmma::load_matrix_sync(a, Ah + k0, 72);
            wmma::load_matrix_sync(bb, Ws + k0 * 96 + w * 16, 96);
            wmma::mma_sync(cc, a, bb, cc);
        }
        wmma::store_matrix_sync(Cs + w * 16, cc, 100, wmma::mem_row_major);
    }
    __syncthreads();

    {
        int r = t >> 5, c2h = t & 31;     // 512 threads = 16 rows x 32 half2
        g_h2b[(row0 + r) * 32 + c2h] =
            __floats2half2_rn(Cs[r * 100 + c2h * 2], Cs[r * 100 + c2h * 2 + 1]);
    }
    if (t < 16) {
        g_ssrc2[row0 + t] = Cs[t * 100 + 64];
        g_sdst2[row0 + t] = Cs[t * 100 + 65];
    }
}

// ---------------- layer-2 aggregation + fused readout ------------------------
__global__ void __launch_bounds__(256) k_node2(const __half2* __restrict__ h2,
                                               const float* __restrict__ b2,
                                               const float* __restrict__ Wl,
                                               const float* __restrict__ bl,
                                               float* __restrict__ out)
{
    __shared__ int2 sP[8][32];
    int warp = (blockIdx.x * blockDim.x + threadIdx.x) >> 5;
    int lane = threadIdx.x & 31;
    int w8   = (threadIdx.x >> 5) & 7;
    if (warp >= NN) return;
    int i = warp;
    int r0 = (i > 0) ? g_cur[i - 1] : 0;
    int r1 = g_cur[i];
    float sd = g_sdst2[i];
    float ex = __expf(fminf(leaky(g_ssrc2[i] + sd), 60.f));

    GatherOut g = gather_node(h2, g_ssrc2, sd, ex, i, r0, r1, sP[w8], lane);

    int sub = lane & 15;
    float4 bv = *(const float4*)&b2[sub * 4];
    float4 wv = *(const float4*)&Wl[sub * 4];
    float s = (g.a0 * g.inv + bv.x) * wv.x + (g.a1 * g.inv + bv.y) * wv.y +
              (g.a2 * g.inv + bv.z) * wv.z + (g.a3 * g.inv + bv.w) * wv.w;
#pragma unroll
    for (int o = 8; o; o >>= 1) s += __shfl_xor_sync(~0u, s, o);
    if (lane == 0) out[i] = s + bl[0];
}

// ---------------- launcher ---------------------------------------------------
static cudaStream_t s_csr = nullptr;
static cudaEvent_t  s_evFork = nullptr, s_evJoin = nullptr;

extern "C" void kernel_launch(void* const* d_in, const int* in_sizes, int n_in,
                              void* d_out, int out_size)
{
    const float* x     = (const float*)d_in[0];
    const int*   eidx  = (const int*)d_in[1];
    const float* W1    = (const float*)d_in[2];
    const float* as1   = (const float*)d_in[3];
    const float* ad1   = (const float*)d_in[4];
    const float* b1    = (const float*)d_in[5];
    const float* W2    = (const float*)d_in[6];
    const float* as2   = (const float*)d_in[7];
    const float* ad2   = (const float*)d_in[8];
    const float* b2    = (const float*)d_in[9];
    const float* Wl    = (const float*)d_in[10];
    const float* bl    = (const float*)d_in[11];
    float* out = (float*)d_out;

    const int4* src4 = (const int4*)eidx;
    const int4* dst4 = (const int4*)(eidx + NE);

    __half2* ha = nullptr;
    __half2* hb = nullptr;
    __half*  w1h = nullptr;
    cudaGetSymbolAddress((void**)&ha, g_h2a);
    cudaGetSymbolAddress((void**)&hb, g_h2b);
    cudaGetSymbolAddress((void**)&w1h, g_W1h);

    if (!s_csr) {
        cudaStreamCreateWithFlags(&s_csr, cudaStreamNonBlocking);
        cudaEventCreateWithFlags(&s_evFork, cudaEventDisableTiming);
        cudaEventCreateWithFlags(&s_evJoin, cudaEventDisableTiming);
    }

    const int LIN_BLOCKS  = (NN + 63) / 64;          // 1563
    const int FUSE_BLOCKS = NN / 16;                 // 6250
    const int WARP_BLOCKS = (NN * 32 + 255) / 256;   // 12500
    const int E8_BLOCKS   = (NE / 8 + 255) / 256;    // 782

    // weight prep (tiny)
    k_prep<<<2, 256>>>(W1, as1, ad1, W2, as2, ad2);

    // fork: CSR build runs concurrently with layer-1 linear
    cudaEventRecord(s_evFork, 0);
    cudaStreamWaitEvent(s_csr, s_evFork, 0);

    k_lin<<<LIN_BLOCKS, 256>>>(x, w1h, ha);

    k_hist<<<E8_BLOCKS, 256, 0, s_csr>>>(dst4);
    k_scan<<<SCAN_NB, 1024, 0, s_csr>>>();
    k_scatter<<<E8_BLOCKS, 256, 0, s_csr>>>(src4, dst4);
    cudaEventRecord(s_evJoin, s_csr);
    cudaStreamWaitEvent(0, s_evJoin, 0);

    // layer-1 aggregation + layer-2 linear (fused)
    k_node_lin<<<FUSE_BLOCKS, 512>>>(ha, b1);
    // layer-2 aggregation + fused readout
    k_node2<<<WARP_BLOCKS, 256>>>(hb, b2, Wl, bl, out);
}